// round 7
// baseline (speedup 1.0000x reference)
#include <cuda_runtime.h>
#include <cuda_fp16.h>
#include <mma.h>
using namespace nvcuda;

#define NF 128
#define MAXN 100000
#define MAXE 2000000

#define LDH 144                      // smem leading dim (halfs): 288B rows, 32B-aligned
#define GEMM_SMEM (128 * LDH * 4)    // 73728 B: 2 fp16 tiles, reused as fp32 C staging

// ---- scratch (device globals: no allocation allowed) ----
__device__ int    g_cnt[MAXN];
__device__ int    g_off[MAXN];
__device__ int    g_fill[MAXN];
__device__ int    g_bsum[1024];
__device__ int    g_src[MAXE];
__device__ float  g_dis[MAXN];
__device__ __half g_h[(size_t)MAXN * NF];
__device__ float  g_agg[(size_t)MAXN * NF];
__device__ float  g_sum[NF];
__device__ float  g_sumsq[NF];
__device__ float  g_shift[NF];
__device__ float  g_scale[NF];
__device__ float  g_beta[NF];

// ---- init ----
__global__ void k_init(int n) {
    int i = blockIdx.x * blockDim.x + threadIdx.x;
    if (i < NF) { g_sum[i] = 0.f; g_sumsq[i] = 0.f; }
    if (i < n) { g_cnt[i] = 0; g_fill[i] = 0; }
}

// ---- degree count over dst ----
__global__ void k_deg(const int* __restrict__ ei, int E) {
    int i = blockIdx.x * blockDim.x + threadIdx.x;
    if (i < E) atomicAdd(&g_cnt[ei[E + i]], 1);
}

// ---- prefix scan; stage 1 also emits dis = rsqrt(deg) ----
__global__ void k_scan_block(int n) {
    __shared__ int sm[256];
    int i = blockIdx.x * 256 + threadIdx.x;
    int v = (i < n) ? g_cnt[i] : 0;
    sm[threadIdx.x] = v; __syncthreads();
    for (int ofs = 1; ofs < 256; ofs <<= 1) {
        int x = (threadIdx.x >= ofs) ? sm[threadIdx.x - ofs] : 0;
        __syncthreads();
        sm[threadIdx.x] += x;
        __syncthreads();
    }
    if (i < n) {
        g_off[i] = sm[threadIdx.x] - v;
        g_dis[i] = rsqrtf((float)(v + 1));
    }
    if (threadIdx.x == 255) g_bsum[blockIdx.x] = sm[255];
}

__global__ void k_scan_top(int nb) {
    __shared__ int sm[1024];
    int t = threadIdx.x;
    int v = (t < nb) ? g_bsum[t] : 0;
    sm[t] = v; __syncthreads();
    for (int ofs = 1; ofs < 1024; ofs <<= 1) {
        int x = (t >= ofs) ? sm[t - ofs] : 0;
        __syncthreads();
        sm[t] += x;
        __syncthreads();
    }
    if (t < nb) g_bsum[t] = sm[t] - v;
}

__global__ void k_scan_add(int n) {
    int i = blockIdx.x * 256 + threadIdx.x;
    if (i < n) g_off[i] += g_bsum[blockIdx.x];
}

// ---- bucket edges by dst ----
__global__ void k_bucket(const int* __restrict__ ei, int E) {
    int i = blockIdx.x * blockDim.x + threadIdx.x;
    if (i < E) {
        int s = ei[i];
        int d = ei[E + i];
        int slot = g_off[d] + atomicAdd(&g_fill[d], 1);
        g_src[slot] = s;
    }
}

// ---- GEMM: h = x @ W via wmma HMMA (fp16 in, fp32 acc, fp16 out) ----
__global__ void __launch_bounds__(256) k_gemm(const float* __restrict__ x,
                                              const float* __restrict__ W, int n) {
    extern __shared__ char smraw[];
    __half* xs = (__half*)smraw;                 // [128][LDH]
    __half* ws = (__half*)smraw + 128 * LDH;     // [128][LDH]
    float*  cs = (float*)smraw;                  // reused as C [128][LDH]

    int tid = threadIdx.x;
    int rowBase = blockIdx.x * 128;

    // stage x tile (fp32 -> fp16) : 128 rows x 32 float4-groups
    for (int i = tid; i < 4096; i += 256) {
        int row = i >> 5;
        int c4 = (i & 31) << 2;
        int gr = rowBase + row;
        float4 v = make_float4(0.f, 0.f, 0.f, 0.f);
        if (gr < n) v = *(const float4*)(x + (size_t)gr * NF + c4);
        __half2 h0 = __floats2half2_rn(v.x, v.y);
        __half2 h1 = __floats2half2_rn(v.z, v.w);
        uint2 pk; pk.x = *(unsigned int*)&h0; pk.y = *(unsigned int*)&h1;
        *(uint2*)(xs + row * LDH + c4) = pk;
    }
    // stage W tile (fp32 -> fp16) : W is [K=128][N=128] row-major
    for (int i = tid; i < 4096; i += 256) {
        int k = i >> 5;
        int c4 = (i & 31) << 2;
        float4 v = *(const float4*)(W + (size_t)k * NF + c4);
        __half2 h0 = __floats2half2_rn(v.x, v.y);
        __half2 h1 = __floats2half2_rn(v.z, v.w);
        uint2 pk; pk.x = *(unsigned int*)&h0; pk.y = *(unsigned int*)&h1;
        *(uint2*)(ws + k * LDH + c4) = pk;
    }
    __syncthreads();

    // warp tiling: 8 warps; warpRow in 0..3 (32 rows), warpCol in 0..1 (64 cols)
    int w = tid >> 5;
    int warpRow = w & 3;
    int warpCol = w >> 2;

    wmma::fragment<wmma::accumulator, 16, 16, 16, float> acc[2][4];
#pragma unroll
    for (int i = 0; i < 2; i++)
#pragma unroll
        for (int j = 0; j < 4; j++) wmma::fill_fragment(acc[i][j], 0.f);

#pragma unroll
    for (int k0 = 0; k0 < 8; k0++) {
        wmma::fragment<wmma::matrix_a, 16, 16, 16, __half, wmma::row_major> a[2];
        wmma::fragment<wmma::matrix_b, 16, 16, 16, __half, wmma::row_major> bfr[4];
#pragma unroll
        for (int i = 0; i < 2; i++)
            wmma::load_matrix_sync(a[i], xs + (warpRow * 32 + i * 16) * LDH + k0 * 16, LDH);
#pragma unroll
        for (int j = 0; j < 4; j++)
            wmma::load_matrix_sync(bfr[j], ws + (k0 * 16) * LDH + warpCol * 64 + j * 16, LDH);
#pragma unroll
        for (int i = 0; i < 2; i++)
#pragma unroll
            for (int j = 0; j < 4; j++)
                wmma::mma_sync(acc[i][j], a[i], bfr[j], acc[i][j]);
    }
    __syncthreads();   // done reading fp16 tiles; reuse smem as fp32 C

#pragma unroll
    for (int i = 0; i < 2; i++)
#pragma unroll
        for (int j = 0; j < 4; j++)
            wmma::store_matrix_sync(cs + (warpRow * 32 + i * 16) * LDH +
                                    warpCol * 64 + j * 16,
                                    acc[i][j], LDH, wmma::mem_row_major);
    __syncthreads();

    // convert C fp32 -> fp16 and write g_h
    for (int i = tid; i < 4096; i += 256) {
        int row = i >> 5;
        int c4 = (i & 31) << 2;
        int gr = rowBase + row;
        if (gr < n) {
            float4 v = *(float4*)(cs + row * LDH + c4);
            __half2 h0 = __floats2half2_rn(v.x, v.y);
            __half2 h1 = __floats2half2_rn(v.z, v.w);
            uint2 pk; pk.x = *(unsigned int*)&h0; pk.y = *(unsigned int*)&h1;
            *(uint2*)(g_h + (size_t)gr * NF + c4) = pk;
        }
    }
}

// ---- CSR aggregate (fp16 gather, fp32 accumulate) + fused stats ----
__global__ void __launch_bounds__(256) k_agg(const float* __restrict__ b, int n) {
    __shared__ float ssum[8 * 128];
    __shared__ float ssq[8 * 128];
    int warpsPerGrid = gridDim.x * 8;
    int w = threadIdx.x >> 5;
    int lane = threadIdx.x & 31;
    float4 bv = *(const float4*)(b + lane * 4);

    float4 ls = make_float4(0.f, 0.f, 0.f, 0.f);
    float4 lq = make_float4(0.f, 0.f, 0.f, 0.f);

    for (int d = blockIdx.x * 8 + w; d < n; d += warpsPerGrid) {
        int beg = g_off[d];
        int cnt = g_cnt[d];
        float dd = g_dis[d];

        uint2 hp = *(const uint2*)(g_h + (size_t)d * NF + lane * 4);
        float2 s0 = __half22float2(*(__half2*)&hp.x);
        float2 s1 = __half22float2(*(__half2*)&hp.y);
        float4 acc = make_float4(s0.x * dd, s0.y * dd, s1.x * dd, s1.y * dd);

        int j = 0;
        for (; j + 8 <= cnt; j += 8) {
            int s[8];
#pragma unroll
            for (int u = 0; u < 8; u++) s[u] = g_src[beg + j + u];
            float wt[8];
#pragma unroll
            for (int u = 0; u < 8; u++) wt[u] = g_dis[s[u]];
            uint2 v[8];
#pragma unroll
            for (int u = 0; u < 8; u++)
                v[u] = *(const uint2*)(g_h + (size_t)s[u] * NF + lane * 4);
#pragma unroll
            for (int u = 0; u < 8; u++) {
                float2 a = __half22float2(*(__half2*)&v[u].x);
                float2 c = __half22float2(*(__half2*)&v[u].y);
                acc.x += wt[u] * a.x; acc.y += wt[u] * a.y;
                acc.z += wt[u] * c.x; acc.w += wt[u] * c.y;
            }
        }
        for (; j < cnt; j++) {
            int s = g_src[beg + j];
            float ww = g_dis[s];
            uint2 vv = *(const uint2*)(g_h + (size_t)s * NF + lane * 4);
            float2 a = __half22float2(*(__half2*)&vv.x);
            float2 c = __half22float2(*(__half2*)&vv.y);
            acc.x += ww * a.x; acc.y += ww * a.y;
            acc.z += ww * c.x; acc.w += ww * c.y;
        }

        float4 o = make_float4(acc.x * dd + bv.x, acc.y * dd + bv.y,
                               acc.z * dd + bv.z, acc.w * dd + bv.w);
        *(float4*)(g_agg + (size_t)d * NF + lane * 4) = o;

        ls.x += o.x; ls.y += o.y; ls.z += o.z; ls.w += o.w;
        lq.x += o.x * o.x; lq.y += o.y * o.y; lq.z += o.z * o.z; lq.w += o.w * o.w;
    }

    *(float4*)(ssum + w * 128 + lane * 4) = ls;
    *(float4*)(ssq + w * 128 + lane * 4) = lq;
    __syncthreads();

    if (threadIdx.x < 128) {
        int f = threadIdx.x;
        float s = 0.f, q = 0.f;
#pragma unroll
        for (int k = 0; k < 8; k++) { s += ssum[k * 128 + f]; q += ssq[k * 128 + f]; }
        atomicAdd(&g_sum[f], s);
        atomicAdd(&g_sumsq[f], q);
    }
}

// ---- finalize stats ----
__global__ void k_fin(const float* __restrict__ gw, const float* __restrict__ gb,
                      const float* __restrict__ gms, float inv_n) {
    int f = threadIdx.x;
    float mean = g_sum[f] * inv_n;
    float ex2 = g_sumsq[f] * inv_n;
    float c = mean * gms[f];
    float var = ex2 - 2.f * c * mean + c * c;
    float sc = rsqrtf(var + 1e-5f) * gw[f];
    g_shift[f] = c;
    g_scale[f] = sc;
    g_beta[f] = gb[f];
}

// ---- normalize + LeakyReLU + edge copy ----
__global__ void k_out(const int* __restrict__ ei, float* __restrict__ out,
                      int n, int m2) {
    int i = blockIdx.x * blockDim.x + threadIdx.x;
    int nodeGroups = n * 32;
    if (i < nodeGroups) {
        int f4 = (i & 31) << 2;
        float4 v = *(const float4*)(g_agg + (size_t)i * 4);
        float4 o;
        o.x = (v.x - g_shift[f4 + 0]) * g_scale[f4 + 0] + g_beta[f4 + 0];
        o.y = (v.y - g_shift[f4 + 1]) * g_scale[f4 + 1] + g_beta[f4 + 1];
        o.z = (v.z - g_shift[f4 + 2]) * g_scale[f4 + 2] + g_beta[f4 + 2];
        o.w = (v.w - g_shift[f4 + 3]) * g_scale[f4 + 3] + g_beta[f4 + 3];
        o.x = o.x > 0.f ? o.x : 0.01f * o.x;
        o.y = o.y > 0.f ? o.y : 0.01f * o.y;
        o.z = o.z > 0.f ? o.z : 0.01f * o.z;
        o.w = o.w > 0.f ? o.w : 0.01f * o.w;
        *(float4*)(out + (size_t)i * 4) = o;
    } else {
        int g = i - nodeGroups;
        int base = g * 4;
        if (base < m2) {
            float* dst = out + (size_t)n * NF + base;
            if (base + 4 <= m2) {
                int4 e = *(const int4*)(ei + base);
                float4 o = make_float4((float)e.x, (float)e.y, (float)e.z, (float)e.w);
                *(float4*)dst = o;
            } else {
                for (int k = 0; base + k < m2; k++) dst[k] = (float)ei[base + k];
            }
        }
    }
}

extern "C" void kernel_launch(void* const* d_in, const int* in_sizes, int n_in,
                              void* d_out, int out_size) {
    const float* x = (const float*)d_in[0];
    const int* ei = (const int*)d_in[1];
    const float* W = (const float*)d_in[2];
    const float* b = (const float*)d_in[3];
    const float* gw = (const float*)d_in[4];
    const float* gb = (const float*)d_in[5];
    const float* gms = (const float*)d_in[6];

    int n = in_sizes[0] / NF;
    int E = in_sizes[1] / 2;
    float* out = (float*)d_out;

    static cudaStream_t s2 = nullptr;
    static cudaEvent_t evFork = nullptr, evJoin = nullptr;
    if (!s2) {
        cudaStreamCreateWithFlags(&s2, cudaStreamNonBlocking);
        cudaEventCreateWithFlags(&evFork, cudaEventDisableTiming);
        cudaEventCreateWithFlags(&evJoin, cudaEventDisableTiming);
        cudaFuncSetAttribute(k_gemm, cudaFuncAttributeMaxDynamicSharedMemorySize,
                             GEMM_SMEM);
    }

    int init_n = (n > NF ? n : NF);
    int NB = (n + 255) / 256;

    cudaEventRecord(evFork, 0);
    cudaStreamWaitEvent(s2, evFork, 0);
    k_gemm<<<(n + 127) / 128, 256, GEMM_SMEM, s2>>>(x, W, n);
    cudaEventRecord(evJoin, s2);

    k_init<<<(init_n + 255) / 256, 256>>>(n);
    k_deg<<<(E + 255) / 256, 256>>>(ei, E);
    k_scan_block<<<NB, 256>>>(n);
    k_scan_top<<<1, 1024>>>(NB);
    k_scan_add<<<NB, 256>>>(n);
    k_bucket<<<(E + 255) / 256, 256>>>(ei, E);

    cudaStreamWaitEvent(0, evJoin, 0);

    int aggBlocks = (n + 7) / 8;
    if (aggBlocks > 1184) aggBlocks = 1184;
    k_agg<<<aggBlocks, 256>>>(b, n);

    k_fin<<<1, 128>>>(gw, gb, gms, 1.0f / (float)n);

    long long extra = (long long)out_size - (long long)n * NF;
    int m2 = 0;
    if (extra > 0) {
        m2 = (int)(extra < (long long)in_sizes[1] ? extra : (long long)in_sizes[1]);
    }
    long long totalThreads = (long long)n * 32 + (m2 + 3) / 4;
    k_out<<<(int)((totalThreads + 255) / 256), 256>>>(ei, out, n, m2);
}